// round 2
// baseline (speedup 1.0000x reference)
#include <cuda_runtime.h>
#include <math.h>

#define H        64
#define NZ       120
#define NLAYERS  4
#define DIMH     256
#define DIMG     65536
#define HIST_BLOCKS  128
#define HIST_THREADS 256

// Scratch (no allocations allowed): per-block histogram partials, the
// count-weighted post-layer table, and the unsymmetrized g vector.
__device__ int   d_part[HIST_BLOCKS * NZ];
__device__ float d_wtab[NZ * H];
__device__ float d_gbuf[DIMG];

// ---------------------------------------------------------------------------
// Kernel 1: per-block histogram of Z, values in [0,120).
// Z may be materialized as int32 OR int64 (reference declares int64; JAX x64
// config decides). Detect at runtime: int64 data read as int32 words has
// every odd word == 0 (values < 120, little-endian). For int32 data the
// chance all 32 sampled odd words are zero is (1/120)^32 ~ 0.
// Shared-memory integer atomics (deterministic), each block writes its own
// partial row of d_part -- no global atomics, no zero-init kernel needed.
// ---------------------------------------------------------------------------
__global__ void k_hist(const int* __restrict__ Z, int n) {
    __shared__ int sh[NZ];
    for (int i = threadIdx.x; i < NZ; i += blockDim.x) sh[i] = 0;
    __syncthreads();

    // dtype sniff (redundant per thread, reads broadcast from L1/L2)
    bool is64 = true;
    #pragma unroll
    for (int i = 0; i < 32; ++i)
        if (Z[2 * i + 1] != 0) { is64 = false; break; }

    const int stride = gridDim.x * blockDim.x;
    const int tid = blockIdx.x * blockDim.x + threadIdx.x;
    const int4* __restrict__ Z4 = (const int4*)Z;

    if (!is64) {
        const int n4 = n >> 2;                 // n = 1,000,000, divisible by 4
        for (int i = tid; i < n4; i += stride) {
            int4 v = Z4[i];
            atomicAdd(&sh[v.x], 1);
            atomicAdd(&sh[v.y], 1);
            atomicAdd(&sh[v.z], 1);
            atomicAdd(&sh[v.w], 1);
        }
    } else {
        const int n2 = n >> 1;                 // int4 covers 2 int64 elements
        for (int i = tid; i < n2; i += stride) {
            int4 v = Z4[i];
            atomicAdd(&sh[v.x], 1);            // low word of elem 0
            atomicAdd(&sh[v.z], 1);            // low word of elem 1
        }
    }
    __syncthreads();
    for (int i = threadIdx.x; i < NZ; i += blockDim.x)
        d_part[blockIdx.x * NZ + i] = sh[i];
}

// ---------------------------------------------------------------------------
// Kernel 2: 120-row table through the 4 tensor-product layers.
// One block per z-value (rows independent across layers), 64 threads.
// Writes the count-weighted row: d_wtab[z] = count[z] * f(embed[z]).
// ---------------------------------------------------------------------------
__global__ void k_table(const float* __restrict__ embed,
                        const float* __restrict__ W_tp) {
    __shared__ float xs[H];
    const int z = blockIdx.x;
    const int j = threadIdx.x;

    xs[j] = embed[z * H + j];
    __syncthreads();

    #pragma unroll
    for (int l = 0; l < NLAYERS; ++l) {
        const float* __restrict__ W = W_tp + l * H * H;
        float acc = 0.f;
        #pragma unroll
        for (int k = 0; k < H; ++k)
            acc = fmaf(xs[k], W[k * H + j], acc);   // xs broadcast, W coalesced
        acc *= 0.125f;                              // INV_SQRT_H = 1/sqrt(64)
        float s = acc / (1.f + expf(-acc));         // silu
        __syncthreads();
        xs[j] = s;
        __syncthreads();
    }

    // Deterministic count reduction (all threads redundantly, L1-broadcast).
    float cnt = 0.f;
    #pragma unroll 8
    for (int b = 0; b < HIST_BLOCKS; ++b)
        cnt += (float)d_part[b * NZ + z];

    d_wtab[z * H + j] = cnt * xs[j];
}

// ---------------------------------------------------------------------------
// Kernel 3 (grid = 257): blocks 0..255 compute g = g_feat @ w_g + b_g into
// d_gbuf (coalesced w_g reads -- the 16.8 MB dominant traffic). Block 256
// computes h = g_feat @ w_h + b_h, symmetrizes it, writes out[0:256].
// Each block first reduces g_feat from d_wtab (L2-resident, fixed order).
// ---------------------------------------------------------------------------
__global__ void k_g(const float* __restrict__ w_g, const float* __restrict__ b_g,
                    const float* __restrict__ w_h, const float* __restrict__ b_h,
                    float* __restrict__ out) {
    __shared__ float gf[H];
    __shared__ float red[256];
    const int t = threadIdx.x;

    // g_feat[j] = sum_z d_wtab[z][j]; 4 partial strips of 30, then combine.
    {
        const int j = t & 63, p = t >> 6;       // 120 = 4 * 30
        float s = 0.f;
        #pragma unroll
        for (int z = p * 30; z < p * 30 + 30; ++z)
            s += d_wtab[z * H + j];
        red[t] = s;
        __syncthreads();
        if (t < 64) gf[t] = red[t] + red[t + 64] + red[t + 128] + red[t + 192];
        __syncthreads();
    }

    if (blockIdx.x < 256) {
        const int i = blockIdx.x * 256 + t;
        float acc = b_g[i];
        #pragma unroll
        for (int k = 0; k < H; ++k)
            acc = fmaf(gf[k], w_g[k * DIMG + i], acc);
        d_gbuf[i] = acc;
    } else {
        float acc = b_h[t];
        #pragma unroll
        for (int k = 0; k < H; ++k)
            acc = fmaf(gf[k], w_h[k * DIMH + t], acc);
        red[t] = acc;                            // h in shared
        __syncthreads();
        const int i = t >> 4, jj = t & 15;
        out[t] = 0.5f * (red[i * 16 + jj] + red[jj * 16 + i]);
    }
}

// ---------------------------------------------------------------------------
// Kernel 4: 8-fold permutation symmetrization of g. d_gbuf (256 KB) is
// L2-resident after kernel 3; 8 gathers per output element.
// out[256 + (a,b,c,d)] = mean over the Z2^3 index group.
// ---------------------------------------------------------------------------
__global__ void k_sym(float* __restrict__ out) {
    const int idx = blockIdx.x * 256 + threadIdx.x;
    const int a = idx >> 12, b = (idx >> 8) & 15, c = (idx >> 4) & 15, d = idx & 15;
#define GIDX(x, y, zz, w) d_gbuf[((x) << 12) | ((y) << 8) | ((zz) << 4) | (w)]
    float s = GIDX(a, b, c, d) + GIDX(b, a, c, d)
            + GIDX(a, b, d, c) + GIDX(b, a, d, c)
            + GIDX(c, d, a, b) + GIDX(d, c, a, b)
            + GIDX(c, d, b, a) + GIDX(d, c, b, a);
#undef GIDX
    out[256 + idx] = 0.125f * s;
}

// ---------------------------------------------------------------------------
// Inputs (metadata order): Z, pos, ghost, embed, W_tp, w_h, b_h, w_g, b_g.
// pos and ghost are dead code in the reference -- never touched.
// ---------------------------------------------------------------------------
extern "C" void kernel_launch(void* const* d_in, const int* in_sizes, int n_in,
                              void* d_out, int out_size) {
    const int*   Z     = (const int*)d_in[0];
    const float* embed = (const float*)d_in[3];
    const float* W_tp  = (const float*)d_in[4];
    const float* w_h   = (const float*)d_in[5];
    const float* b_h   = (const float*)d_in[6];
    const float* w_g   = (const float*)d_in[7];
    const float* b_g   = (const float*)d_in[8];
    float* out = (float*)d_out;
    const int n = in_sizes[0];

    k_hist <<<HIST_BLOCKS, HIST_THREADS>>>(Z, n);
    k_table<<<NZ, H>>>(embed, W_tp);
    k_g    <<<257, 256>>>(w_g, b_g, w_h, b_h, out);
    k_sym  <<<256, 256>>>(out);
}